// round 6
// baseline (speedup 1.0000x reference)
#include <cuda_runtime.h>
#include <cuda_bf16.h>
#include <float.h>
#include <math.h>

// Problem constants
#define BATCH 8
#define NPTS  4096
#define KNN_K 16
#define TOTAL_PTS (BATCH * NPTS)   // 32768

// ---------------- scratch (static device memory; no allocation) ----------------
__device__ float    g_bufA[TOTAL_PTS * 128];   // 16 MB
__device__ float    g_bufB[TOTAL_PTS * 128];   // 16 MB
__device__ float    g_feat[TOTAL_PTS * 12];
__device__ int      g_idx[TOTAL_PTS * KNN_K];
__device__ unsigned g_gmax[BATCH * 1024];
__device__ float    g_h[BATCH * 512];

// ---------------- float <-> ordered-uint encoding for atomicMax ----------------
__device__ __forceinline__ unsigned fenc(float f) {
    unsigned u = __float_as_uint(f);
    return (u & 0x80000000u) ? ~u : (u | 0x80000000u);
}
__device__ __forceinline__ float fdec(unsigned u) {
    unsigned v = (u & 0x80000000u) ? (u & 0x7fffffffu) : ~u;
    return __uint_as_float(v);
}

// ---------------- KNN: top-16 by pd = 2*dot - xx_n - xx_m (desc), stable ties --
__global__ void knn_kernel(const float* __restrict__ pts) {
    const int b  = blockIdx.x >> 5;              // 32 blocks per batch
    const int n  = ((blockIdx.x & 31) << 7) + threadIdx.x;
    const float* px = pts + b * 3 * NPTS;

    const float xn = px[n], yn = px[NPTS + n], zn = px[2 * NPTS + n];
    const float xxn = fmaf(xn, xn, fmaf(yn, yn, zn * zn));

    float kd[16]; int ki[16];
#pragma unroll
    for (int j = 0; j < 16; j++) { kd[j] = -FLT_MAX; ki[j] = 0; }

    __shared__ float4 tile[2048];

    for (int m0 = 0; m0 < NPTS; m0 += 2048) {
        __syncthreads();
        for (int t = threadIdx.x; t < 2048; t += 128) {
            int m = m0 + t;
            float x = px[m], y = px[NPTS + m], z = px[2 * NPTS + m];
            tile[t] = make_float4(x, y, z, fmaf(x, x, fmaf(y, y, z * z)));
        }
        __syncthreads();
        for (int t = 0; t < 2048; t++) {
            float4 pm = tile[t];
            float dot = fmaf(xn, pm.x, fmaf(yn, pm.y, zn * pm.z));
            float d = fmaf(2.0f, dot, (-xxn) - pm.w);   // m==n -> exactly 0
            if (d > kd[15]) {
                // Guarded insertion. Strict '<' on the shift keeps equal keys in
                // index order (stable, matches lax.top_k tie-breaking).
                const int ci = m0 + t;
                bool done = false;
#pragma unroll
                for (int j = 15; j > 0; --j) {
                    if (!done) {
                        if (kd[j - 1] < d) {
                            kd[j] = kd[j - 1]; ki[j] = ki[j - 1];
                            if (j == 1) { kd[0] = d; ki[0] = ci; }
                        } else {
                            kd[j] = d; ki[j] = ci;
                            done = true;
                        }
                    }
                }
            }
        }
    }
    int* op = g_idx + (b * NPTS + n) * KNN_K;
#pragma unroll
    for (int j = 0; j < 16; j++) op[j] = ki[j];
}

// ---------------- local covariance features: [p][12] --------------------------
__global__ void feat_kernel(const float* __restrict__ pts) {
    int p = blockIdx.x * 256 + threadIdx.x;
    if (p >= TOTAL_PTS) return;
    int b = p >> 12, n = p & (NPTS - 1);
    const float* px = pts + b * 3 * NPTS;
    int i0 = g_idx[p * KNN_K + 0];
    int i1 = g_idx[p * KNN_K + 1];
    float a0 = px[i0], a1 = px[NPTS + i0], a2 = px[2 * NPTS + i0];
    float c0 = px[i1], c1 = px[NPTS + i1], c2 = px[2 * NPTS + i1];
    float* f = g_feat + p * 12;
    f[0] = px[n]; f[1] = px[NPTS + n]; f[2] = px[2 * NPTS + n];
    f[3] = a0 * c0; f[4]  = a0 * c1; f[5]  = a0 * c2;
    f[6] = a1 * c0; f[7]  = a1 * c1; f[8]  = a1 * c2;
    f[9] = a2 * c0; f[10] = a2 * c1; f[11] = a2 * c2;
}

// ---------------- generic pointwise dense layer --------------------------------
// out[p][o] = act( sum_i W[o][i] * in[p][i] + b[o] ),  64 points per block
template <int DIN, int DOUT, bool RELU>
__global__ void dense_kernel(const float* __restrict__ in, const float* __restrict__ W,
                             const float* __restrict__ bias, float* __restrict__ out) {
    constexpr int SW = DOUT + 4;                // padded transposed weight row
    extern __shared__ float sm[];
    float* sW  = sm;                            // DIN * SW   (sW[i][oc])
    float* sB  = sW + DIN * SW;                 // DOUT
    float* sIn = sB + DOUT;                     // 64 * (DIN+1)
    const int tid = threadIdx.x;

    for (int t = tid; t < DIN * DOUT; t += 64) {
        int oc = t / DIN, i = t - oc * DIN;     // coalesced global read
        sW[i * SW + oc] = W[t];
    }
    for (int t = tid; t < DOUT; t += 64) sB[t] = bias[t];
    const int p0 = blockIdx.x * 64;
    for (int t = tid; t < 64 * DIN; t += 64) {
        int r = t / DIN, c = t - r * DIN;
        sIn[r * (DIN + 1) + c] = in[(size_t)(p0 + r) * DIN + c];
    }
    __syncthreads();

    const float* myin = sIn + tid * (DIN + 1);
    float* op = out + (size_t)(p0 + tid) * DOUT;

#pragma unroll 1
    for (int oc0 = 0; oc0 < DOUT; oc0 += 16) {
        float acc[16];
#pragma unroll
        for (int j = 0; j < 16; j++) acc[j] = sB[oc0 + j];
#pragma unroll 4
        for (int i = 0; i < DIN; i++) {
            float xi = myin[i];
            const float4* wr = (const float4*)(sW + i * SW + oc0);
#pragma unroll
            for (int q = 0; q < 4; q++) {
                float4 w4 = wr[q];
                acc[q * 4 + 0] = fmaf(w4.x, xi, acc[q * 4 + 0]);
                acc[q * 4 + 1] = fmaf(w4.y, xi, acc[q * 4 + 1]);
                acc[q * 4 + 2] = fmaf(w4.z, xi, acc[q * 4 + 2]);
                acc[q * 4 + 3] = fmaf(w4.w, xi, acc[q * 4 + 3]);
            }
        }
#pragma unroll
        for (int q = 0; q < 4; q++) {
            float4 v;
            v.x = acc[q * 4 + 0]; v.y = acc[q * 4 + 1];
            v.z = acc[q * 4 + 2]; v.w = acc[q * 4 + 3];
            if (RELU) {
                v.x = fmaxf(v.x, 0.f); v.y = fmaxf(v.y, 0.f);
                v.z = fmaxf(v.z, 0.f); v.w = fmaxf(v.w, 0.f);
            }
            ((float4*)(op + oc0))[q] = v;
        }
    }
}

// ---------------- neighbor max-pool over idx (float4 vectorized) -----------------
// Each thread owns 4 consecutive channels of one point.
template <int D>
__global__ void maxpool_kernel(const float* __restrict__ in, float* __restrict__ out) {
    constexpr int DV = D / 4;                   // float4 groups per point
    int t = blockIdx.x * 256 + threadIdx.x;
    if (t >= TOTAL_PTS * DV) return;
    int p = t / DV;
    int c4 = t - p * DV;                        // float4 group index
    int base = (p >> 12) << 12;                 // b * NPTS
    const int* id = g_idx + p * KNN_K;
    float4 m = make_float4(-FLT_MAX, -FLT_MAX, -FLT_MAX, -FLT_MAX);
#pragma unroll
    for (int k = 0; k < KNN_K; k++) {
        int j = id[k];
        float4 v = *(const float4*)(in + (size_t)(base + j) * D + c4 * 4);
        m.x = fmaxf(m.x, v.x); m.y = fmaxf(m.y, v.y);
        m.z = fmaxf(m.z, v.z); m.w = fmaxf(m.w, v.w);
    }
    ((float4*)out)[t] = m;
}

// ---------------- reset gmax -----------------------------------------------------
__global__ void reset_kernel() {
    int t = blockIdx.x * 256 + threadIdx.x;
    if (t < BATCH * 1024) g_gmax[t] = 0u;
}

// ---------------- c2 (128->1024) GEMM + global max over points -------------------
// grid: (256 point-tiles, 8 oc-tiles), 256 threads, 8x8 microtiles
__global__ void c2max_kernel(const float* __restrict__ y, const float* __restrict__ W,
                             const float* __restrict__ bias) {
    extern __shared__ float sm[];
    float* sW = sm;                 // [i][oc] stride 132
    float* sX = sW + 128 * 132;     // [i][p]  stride 132
    float* sB = sX + 128 * 132;     // 128
    const int tid = threadIdx.x;
    const int pt0 = blockIdx.x * 128;
    const int oc0 = blockIdx.y * 128;
    const int b = pt0 >> 12;

    for (int t = tid; t < 16384; t += 256) {
        int r = t >> 7, i = t & 127;            // coalesced reads (i fastest)
        sW[i * 132 + r] = W[(size_t)(oc0 + r) * 128 + i];
        sX[i * 132 + r] = y[(size_t)(pt0 + r) * 128 + i];
    }
    if (tid < 128) sB[tid] = bias[oc0 + tid];
    __syncthreads();

    const int tx = tid & 15, ty = tid >> 4;
    float acc[8][8];
#pragma unroll
    for (int j = 0; j < 8; j++)
#pragma unroll
        for (int k = 0; k < 8; k++) acc[j][k] = 0.f;

#pragma unroll 2
    for (int i = 0; i < 128; i++) {
        const float* wr = sW + i * 132 + ty * 8;
        const float* xr = sX + i * 132 + tx * 8;
        float4 w0 = *(const float4*)(wr);
        float4 w1 = *(const float4*)(wr + 4);
        float4 x0 = *(const float4*)(xr);
        float4 x1 = *(const float4*)(xr + 4);
        float wv[8] = {w0.x, w0.y, w0.z, w0.w, w1.x, w1.y, w1.z, w1.w};
        float xv[8] = {x0.x, x0.y, x0.z, x0.w, x1.x, x1.y, x1.z, x1.w};
#pragma unroll
        for (int j = 0; j < 8; j++)
#pragma unroll
            for (int k = 0; k < 8; k++)
                acc[j][k] = fmaf(wv[j], xv[k], acc[j][k]);
    }

#pragma unroll
    for (int j = 0; j < 8; j++) {
        float m = acc[j][0];
#pragma unroll
        for (int k = 1; k < 8; k++) m = fmaxf(m, acc[j][k]);
        m += sB[ty * 8 + j];
#pragma unroll
        for (int off = 8; off >= 1; off >>= 1)
            m = fmaxf(m, __shfl_xor_sync(0xffffffffu, m, off));
        if (tx == 0)
            atomicMax(&g_gmax[b * 1024 + oc0 + ty * 8 + j], fenc(m));
    }
}

// ---------------- mlp2 -----------------------------------------------------------
__global__ void mlp2a_kernel(const float* __restrict__ w, const float* __restrict__ bias) {
    int b = blockIdx.x;
    __shared__ float sg[1024];
    for (int t = threadIdx.x; t < 1024; t += 256) sg[t] = fdec(g_gmax[b * 1024 + t]);
    __syncthreads();
    for (int o = threadIdx.x; o < 512; o += 256) {
        float acc = bias[o];
        const float* wr = w + (size_t)o * 1024;
#pragma unroll 8
        for (int i = 0; i < 1024; i++) acc = fmaf(wr[i], sg[i], acc);
        g_h[b * 512 + o] = fmaxf(acc, 0.f);
    }
}

__global__ void mlp2b_kernel(const float* __restrict__ w, const float* __restrict__ bias,
                             float* __restrict__ out) {
    int b = blockIdx.x;
    __shared__ float sh[512];
    if (threadIdx.x < 512) sh[threadIdx.x] = g_h[b * 512 + threadIdx.x];
    __syncthreads();
    int o = threadIdx.x;
    if (o < 512) {
        float acc = bias[o];
        const float* wr = w + (size_t)o * 512;
#pragma unroll 8
        for (int i = 0; i < 512; i++) acc = fmaf(wr[i], sh[i], acc);
        out[b * 512 + o] = acc;
    }
}

// ---------------- launch ---------------------------------------------------------
extern "C" void kernel_launch(void* const* d_in, const int* in_sizes, int n_in,
                              void* d_out, int out_size) {
    const float* pts  = (const float*)d_in[0];
    const float* m1w1 = (const float*)d_in[1];  const float* m1b1 = (const float*)d_in[2];
    const float* m1w2 = (const float*)d_in[3];  const float* m1b2 = (const float*)d_in[4];
    const float* m1w3 = (const float*)d_in[5];  const float* m1b3 = (const float*)d_in[6];
    const float* l1w  = (const float*)d_in[7];  const float* l1b  = (const float*)d_in[8];
    const float* c1w  = (const float*)d_in[9];  const float* c1b  = (const float*)d_in[10];
    const float* l2w  = (const float*)d_in[11]; const float* l2b  = (const float*)d_in[12];
    const float* c2w  = (const float*)d_in[13]; const float* c2b  = (const float*)d_in[14];
    const float* m2w1 = (const float*)d_in[15]; const float* m2b1 = (const float*)d_in[16];
    const float* m2w2 = (const float*)d_in[17]; const float* m2b2 = (const float*)d_in[18];
    float* out = (float*)d_out;

    float *bufA = nullptr, *bufB = nullptr, *feat = nullptr;
    cudaGetSymbolAddress((void**)&bufA, g_bufA);
    cudaGetSymbolAddress((void**)&bufB, g_bufB);
    cudaGetSymbolAddress((void**)&feat, g_feat);

    // dynamic smem sizes
    const int smem_d12_64   = (12 * 68 + 64 + 64 * 13) * 4;
    const int smem_d64_64   = (64 * 68 + 64 + 64 * 65) * 4;
    const int smem_d64_128  = (64 * 132 + 128 + 64 * 65) * 4;
    const int smem_d128_128 = (128 * 132 + 128 + 64 * 129) * 4;
    const int smem_c2       = (2 * 128 * 132 + 128) * 4;

    cudaFuncSetAttribute(dense_kernel<64, 128, true>,
                         cudaFuncAttributeMaxDynamicSharedMemorySize, smem_d64_128);
    cudaFuncSetAttribute(dense_kernel<128, 128, false>,
                         cudaFuncAttributeMaxDynamicSharedMemorySize, smem_d128_128);
    cudaFuncSetAttribute(c2max_kernel,
                         cudaFuncAttributeMaxDynamicSharedMemorySize, smem_c2);

    // 1. KNN
    knn_kernel<<<BATCH * (NPTS / 128), 128>>>(pts);
    // 2. features
    feat_kernel<<<TOTAL_PTS / 256, 256>>>(pts);
    // 3. mlp1
    dense_kernel<12, 64, true><<<TOTAL_PTS / 64, 64, smem_d12_64>>>(feat, m1w1, m1b1, bufA);
    dense_kernel<64, 64, true><<<TOTAL_PTS / 64, 64, smem_d64_64>>>(bufA, m1w2, m1b2, bufB);
    dense_kernel<64, 64, true><<<TOTAL_PTS / 64, 64, smem_d64_64>>>(bufB, m1w3, m1b3, bufA);
    // 4. graph layer
    maxpool_kernel<64><<<TOTAL_PTS * (64 / 4) / 256, 256>>>(bufA, bufB);
    dense_kernel<64, 64, false><<<TOTAL_PTS / 64, 64, smem_d64_64>>>(bufB, l1w, l1b, bufA);
    dense_kernel<64, 128, true><<<TOTAL_PTS / 64, 64, smem_d64_128>>>(bufA, c1w, c1b, bufB);
    maxpool_kernel<128><<<TOTAL_PTS * (128 / 4) / 256, 256>>>(bufB, bufA);
    dense_kernel<128, 128, false><<<TOTAL_PTS / 64, 64, smem_d128_128>>>(bufA, l2w, l2b, bufB);
    // 5. c2 + global max
    reset_kernel<<<(BATCH * 1024 + 255) / 256, 256>>>();
    {
        dim3 grid(TOTAL_PTS / 128, 8);
        c2max_kernel<<<grid, 256, smem_c2>>>(bufB, c2w, c2b);
    }
    // 6. mlp2
    mlp2a_kernel<<<BATCH, 256>>>(m2w1, m2b1);
    mlp2b_kernel<<<BATCH, 512>>>(m2w2, m2b2, out);
}